// round 9
// baseline (speedup 1.0000x reference)
#include <cuda_runtime.h>
#include <math.h>

// DiffJPEG forward: fused kernel, thread-quad per 8x8 block, TWO independent
// block-chains per thread (16-row double-strip CTA) for latency hiding.
// img: (16,3,512,512) f32, quality: int scalar, out: (16,3,512,512) f32.

#define IMG_W 512
#define IMG_H 512
#define BATCH 16
#define NTHREADS 768
#define STRIP_FLOATS (192 * 72)            // 13824 floats per 8-row strip
#define SMEM_FLOATS (2 * STRIP_FLOATS)     // 27648
#define SMEM_BYTES  (SMEM_FLOATS * 4)      // 110592 (dynamic)

#define MAGIC 12582912.0f                  // 1.5 * 2^23: round-to-nearest-even

// Orthonormal 8-pt DCT-II butterfly constants (double-derived)
#define CA  0.35355339059327373f
#define CB1 0.46193976625564337f
#define CB3 0.19134171618254492f
#define CD1 0.49039264020161522f
#define CD3 0.41573480615127262f
#define CD5 0.27778511650980114f
#define CD7 0.09754516100806413f

#define FDCT8(x0,x1,x2,x3,x4,x5,x6,x7) do {                                  \
    float e0=(x0)+(x7), e1=(x1)+(x6), e2=(x2)+(x5), e3=(x3)+(x4);            \
    float o0=(x0)-(x7), o1=(x1)-(x6), o2=(x2)-(x5), o3=(x3)-(x4);            \
    float ee0=e0+e3, ee1=e1+e2, eo0=e0-e3, eo1=e1-e2;                        \
    (x0) = CA*(ee0+ee1);                                                     \
    (x4) = CA*(ee0-ee1);                                                     \
    (x2) = CB1*eo0 + CB3*eo1;                                                \
    (x6) = CB3*eo0 - CB1*eo1;                                                \
    (x1) = CD1*o0 + CD3*o1 + CD5*o2 + CD7*o3;                                \
    (x3) = CD3*o0 - CD7*o1 - CD1*o2 - CD5*o3;                                \
    (x5) = CD5*o0 - CD1*o1 + CD7*o2 + CD3*o3;                                \
    (x7) = CD7*o0 - CD5*o1 + CD3*o2 - CD1*o3;                                \
} while(0)

#define IDCT8(x0,x1,x2,x3,x4,x5,x6,x7) do {                                  \
    float ee0 = CA*((x0)+(x4)), ee1 = CA*((x0)-(x4));                        \
    float eo0 = CB1*(x2) + CB3*(x6), eo1 = CB3*(x2) - CB1*(x6);              \
    float o0 = CD1*(x1) + CD3*(x3) + CD5*(x5) + CD7*(x7);                    \
    float o1 = CD3*(x1) - CD7*(x3) - CD1*(x5) - CD5*(x7);                    \
    float o2 = CD5*(x1) - CD1*(x3) + CD7*(x5) + CD3*(x7);                    \
    float o3 = CD7*(x1) - CD5*(x3) + CD3*(x5) - CD1*(x7);                    \
    float e0=ee0+eo0, e3=ee0-eo0, e1=ee1+eo1, e2=ee1-eo1;                    \
    (x0)=e0+o0; (x7)=e0-o0; (x1)=e1+o1; (x6)=e1-o1;                          \
    (x2)=e2+o2; (x5)=e2-o2; (x3)=e3+o3; (x4)=e3-o3;                          \
} while(0)

__constant__ float c_lum[64] = {
    16, 11, 10, 16, 24, 40, 51, 61,
    12, 12, 14, 19, 26, 58, 60, 55,
    14, 13, 16, 24, 40, 57, 69, 56,
    14, 17, 22, 29, 51, 87, 80, 62,
    18, 22, 37, 56, 68, 109, 103, 77,
    24, 35, 55, 64, 81, 104, 113, 92,
    49, 64, 78, 87, 103, 121, 120, 101,
    72, 92, 95, 98, 112, 100, 103, 99
};
__constant__ float c_chrom[64] = {
    17, 18, 24, 47, 99, 99, 99, 99,
    18, 21, 26, 66, 99, 99, 99, 99,
    24, 26, 56, 99, 99, 99, 99, 99,
    47, 66, 99, 99, 99, 99, 99, 99,
    99, 99, 99, 99, 99, 99, 99, 99,
    99, 99, 99, 99, 99, 99, 99, 99,
    99, 99, 99, 99, 99, 99, 99, 99,
    99, 99, 99, 99, 99, 99, 99, 99
};

__global__ void __launch_bounds__(NTHREADS, 1)
jpeg_kernel(const float* __restrict__ img,
            const int* __restrict__ quality,
            float* __restrict__ out)
{
    extern __shared__ float sm[];
    // zipped quant tables: float4 (q0, 1/q0, q1, 1/q1) at index l*5+kp
    __shared__ __align__(16) float qzipL[160];
    __shared__ __align__(16) float qzipC[160];

    const int tid = threadIdx.x;

    if (tid < 256) {
        int t = tid >> 7;                 // 0 lum, 1 chrom
        int rem = tid & 127;
        int l = rem >> 4;
        int kp = (rem >> 2) & 3;
        int comp = rem & 3;               // 0:q0 1:r0 2:q1 3:r1
        int k = 2 * kp + (comp >> 1);
        int q = *quality;
        q = max(1, min(100, q));
        float scale = (q < 50) ? (5000.0f / (float)q) : (200.0f - 2.0f * (float)q);
        float base = t ? c_chrom[k * 8 + l] : c_lum[k * 8 + l];
        float v = (base * scale + 50.0f) / 100.0f;
        v = fminf(fmaxf(v, 1.0f), 255.0f);
        float outv = (comp & 1) ? (1.0f / v) : v;
        (t ? qzipC : qzipL)[(l * 5 + kp) * 4 + comp] = outv;
    }

    const int b = blockIdx.x >> 5;         // batch
    const int dstrip = blockIdx.x & 31;    // 16-row double strip
    const int row0 = dstrip * 16;
    const size_t CH = (size_t)IMG_H * IMG_W;
    const size_t img_base = (size_t)b * 3 * CH;

    // ---- Phase A: load 16 rows + RGB->YCbCr into block-slot smem ----
    #pragma unroll
    for (int g = 0; g < 3; g++) {
        int idx = tid + g * NTHREADS;
        if (idx < 2048) {
            int r = idx >> 7;                      // 0..15
            int col = (idx & 127) << 2;
            size_t off = img_base + (size_t)(row0 + r) * IMG_W + col;
            float4 r4 = *(const float4*)(img + off);
            float4 g4 = *(const float4*)(img + off + CH);
            float4 b4 = *(const float4*)(img + off + 2 * CH);
            float4 y4, cb4, cr4;
            {
                const float* Rp = &r4.x; const float* Gp = &g4.x; const float* Bp = &b4.x;
                float* Yp = &y4.x; float* Cbp = &cb4.x; float* Crp = &cr4.x;
                #pragma unroll
                for (int j = 0; j < 4; j++) {
                    float R = Rp[j], G = Gp[j], B = Bp[j];
                    Yp[j]  = fmaf(76.245f, R, fmaf(149.685f, G, 29.07f * B));
                    Cbp[j] = fmaf(-43.0185f, R, fmaf(-84.4815f, G, fmaf(127.5f, B, 128.0f)));
                    Crp[j] = fmaf(127.5f, R, fmaf(-106.7685f, G, fmaf(-20.7315f, B, 128.0f)));
                }
            }
            int rs = r & 7;
            int blk = col >> 3;
            int sb = (r >> 3) * STRIP_FLOATS + blk * 72
                   + (rs >> 2) * 36 + (rs & 3) * 8 + (col & 7);
            *(float4*)(sm + sb)             = y4;
            *(float4*)(sm + 64 * 72 + sb)   = cb4;
            *(float4*)(sm + 128 * 72 + sb)  = cr4;
        }
    }
    __syncthreads();

    // ---- Phase B: thread quad per 8x8 block, 2 independent strips ----
    {
        const int unit = tid >> 2;          // 0..191 (c*64 + blk)
        const int q = tid & 3;              // row-pair index
        const int c = unit >> 6;
        float* ub[2] = { sm + unit * 72, sm + STRIP_FLOATS + unit * 72 };

        float x[2][2][8];                   // [strip][row][col]
        #pragma unroll
        for (int s = 0; s < 2; s++) {
            #pragma unroll
            for (int i = 0; i < 2; i++) {
                int a = 2 * q + i;
                float* rp = ub[s] + (a >> 2) * 36 + (a & 3) * 8;
                float4 v0 = *(const float4*)(rp);
                float4 v1 = *(const float4*)(rp + 4);
                x[s][i][0]=v0.x; x[s][i][1]=v0.y; x[s][i][2]=v0.z; x[s][i][3]=v0.w;
                x[s][i][4]=v1.x; x[s][i][5]=v1.y; x[s][i][6]=v1.z; x[s][i][7]=v1.w;
            }
        }
        #pragma unroll
        for (int s = 0; s < 2; s++)
            #pragma unroll
            for (int i = 0; i < 2; i++)
                FDCT8(x[s][i][0],x[s][i][1],x[s][i][2],x[s][i][3],
                      x[s][i][4],x[s][i][5],x[s][i][6],x[s][i][7]);

        __syncwarp();
        #pragma unroll
        for (int s = 0; s < 2; s++)
            #pragma unroll
            for (int l = 0; l < 8; l++)
                *(float2*)(ub[s] + (l >> 2) * 36 + (l & 3) * 8 + 2 * q)
                    = make_float2(x[s][0][l], x[s][1][l]);
        __syncwarp();

        float y[2][2][8];
        #pragma unroll
        for (int s = 0; s < 2; s++) {
            #pragma unroll
            for (int j = 0; j < 2; j++) {
                int l = 2 * q + j;
                float* rp = ub[s] + (l >> 2) * 36 + (l & 3) * 8;
                float4 v0 = *(const float4*)(rp);
                float4 v1 = *(const float4*)(rp + 4);
                y[s][j][0]=v0.x; y[s][j][1]=v0.y; y[s][j][2]=v0.z; y[s][j][3]=v0.w;
                y[s][j][4]=v1.x; y[s][j][5]=v1.y; y[s][j][6]=v1.z; y[s][j][7]=v1.w;
            }
        }
        #pragma unroll
        for (int s = 0; s < 2; s++)
            #pragma unroll
            for (int j = 0; j < 2; j++)
                FDCT8(y[s][j][0],y[s][j][1],y[s][j][2],y[s][j][3],
                      y[s][j][4],y[s][j][5],y[s][j][6],y[s][j][7]);

        // -128 input shift commutes to DC only
        if (q == 0) { y[0][0][0] -= 1024.0f; y[1][0][0] -= 1024.0f; }

        // quantize: zipped LDS.128 + fmaf magic round (shared across strips)
        {
            const float* qz = ((b * 3 + c) < BATCH) ? qzipL : qzipC;
            #pragma unroll
            for (int j = 0; j < 2; j++) {
                int l = 2 * q + j;
                const float4* zl = (const float4*)(qz + l * 20);
                #pragma unroll
                for (int kp = 0; kp < 4; kp++) {
                    float4 z = zl[kp];
                    #pragma unroll
                    for (int s = 0; s < 2; s++) {
                        float t0 = fmaf(y[s][j][2*kp],   z.y, MAGIC);
                        float t1 = fmaf(y[s][j][2*kp+1], z.w, MAGIC);
                        t0 = __fadd_rn(t0, -MAGIC);
                        t1 = __fadd_rn(t1, -MAGIC);
                        y[s][j][2*kp]   = t0 * z.x;
                        y[s][j][2*kp+1] = t1 * z.z;
                    }
                }
            }
        }

        if (q == 0) { y[0][0][0] += 1024.0f; y[1][0][0] += 1024.0f; }

        #pragma unroll
        for (int s = 0; s < 2; s++)
            #pragma unroll
            for (int j = 0; j < 2; j++)
                IDCT8(y[s][j][0],y[s][j][1],y[s][j][2],y[s][j][3],
                      y[s][j][4],y[s][j][5],y[s][j][6],y[s][j][7]);

        __syncwarp();
        #pragma unroll
        for (int s = 0; s < 2; s++)
            #pragma unroll
            for (int i = 0; i < 8; i++)
                *(float2*)(ub[s] + (i >> 2) * 36 + (i & 3) * 8 + 2 * q)
                    = make_float2(y[s][0][i], y[s][1][i]);
        __syncwarp();

        #pragma unroll
        for (int s = 0; s < 2; s++) {
            #pragma unroll
            for (int i = 0; i < 2; i++) {
                int a = 2 * q + i;
                float* rp = ub[s] + (a >> 2) * 36 + (a & 3) * 8;
                float4 v0 = *(const float4*)(rp);
                float4 v1 = *(const float4*)(rp + 4);
                x[s][i][0]=v0.x; x[s][i][1]=v0.y; x[s][i][2]=v0.z; x[s][i][3]=v0.w;
                x[s][i][4]=v1.x; x[s][i][5]=v1.y; x[s][i][6]=v1.z; x[s][i][7]=v1.w;
            }
        }
        #pragma unroll
        for (int s = 0; s < 2; s++)
            #pragma unroll
            for (int i = 0; i < 2; i++)
                IDCT8(x[s][i][0],x[s][i][1],x[s][i][2],x[s][i][3],
                      x[s][i][4],x[s][i][5],x[s][i][6],x[s][i][7]);

        // pixel store targets exactly the T2 rows only THIS lane read
        #pragma unroll
        for (int s = 0; s < 2; s++) {
            #pragma unroll
            for (int i = 0; i < 2; i++) {
                int a = 2 * q + i;
                float* rp = ub[s] + (a >> 2) * 36 + (a & 3) * 8;
                *(float4*)(rp)     = make_float4(x[s][i][0],x[s][i][1],x[s][i][2],x[s][i][3]);
                *(float4*)(rp + 4) = make_float4(x[s][i][4],x[s][i][5],x[s][i][6],x[s][i][7]);
            }
        }
    }
    __syncthreads();

    // ---- Phase C: YCbCr->RGB, clip, store (16 rows) ----
    #pragma unroll
    for (int g = 0; g < 3; g++) {
        int idx = tid + g * NTHREADS;
        if (idx < 2048) {
            int r = idx >> 7;
            int col = (idx & 127) << 2;
            int rs = r & 7;
            int blk = col >> 3;
            int sb = (r >> 3) * STRIP_FLOATS + blk * 72
                   + (rs >> 2) * 36 + (rs & 3) * 8 + (col & 7);
            float4 y4  = *(const float4*)(sm + sb);
            float4 cb4 = *(const float4*)(sm + 64 * 72 + sb);
            float4 cr4 = *(const float4*)(sm + 128 * 72 + sb);
            float4 ro, go, bo;
            {
                const float* Yp = &y4.x; const float* Cbp = &cb4.x; const float* Crp = &cr4.x;
                float* Rp = &ro.x; float* Gp = &go.x; float* Bp = &bo.x;
                #pragma unroll
                for (int j = 0; j < 4; j++) {
                    float y  = Yp[j];
                    float cb = Cbp[j] - 128.0f;
                    float cr = Crp[j] - 128.0f;
                    float rr = y + 1.402f * cr;
                    float gg = y - 0.34414f * cb - 0.71414f * cr;
                    float bb = y + 1.772f * cb;
                    Rp[j] = fminf(fmaxf(rr * (1.0f / 255.0f), 0.0f), 1.0f);
                    Gp[j] = fminf(fmaxf(gg * (1.0f / 255.0f), 0.0f), 1.0f);
                    Bp[j] = fminf(fmaxf(bb * (1.0f / 255.0f), 0.0f), 1.0f);
                }
            }
            size_t off = img_base + (size_t)(row0 + r) * IMG_W + col;
            *(float4*)(out + off)          = ro;
            *(float4*)(out + off + CH)     = go;
            *(float4*)(out + off + 2 * CH) = bo;
        }
    }
}

extern "C" void kernel_launch(void* const* d_in, const int* in_sizes, int n_in,
                              void* d_out, int out_size)
{
    const float* img = (const float*)d_in[0];
    const int* quality = (const int*)d_in[1];
    float* out = (float*)d_out;

    cudaFuncSetAttribute(jpeg_kernel,
                         cudaFuncAttributeMaxDynamicSharedMemorySize,
                         SMEM_BYTES);

    dim3 grid(BATCH * 32);   // 512 CTAs: (batch, 16-row double strip)
    jpeg_kernel<<<grid, NTHREADS, SMEM_BYTES>>>(img, quality, out);
}

// round 10
// speedup vs baseline: 1.2470x; 1.2470x over previous
#include <cuda_runtime.h>
#include <math.h>

// DiffJPEG forward: fused persistent kernel, thread-quad per 8x8 block,
// zipped quant tables + fmaf magic rounding (R8 structure + task loop).
// img: (16,3,512,512) f32, quality: int scalar, out: (16,3,512,512) f32.

#define IMG_W 512
#define IMG_H 512
#define BATCH 16
#define NTHREADS 768
#define NTASKS 1024                        // batch * 64 strips
#define NRESIDENT 296                      // 148 SMs * 2 CTAs
// smem slot: addr(unit,a,b) = unit*72 + (a>>2)*36 + (a&3)*8 + b
#define SMEM_FLOATS (192 * 72)             // 13824
#define SMEM_BYTES  (SMEM_FLOATS * 4)      // 55296

#define MAGIC 12582912.0f                  // 1.5 * 2^23: round-to-nearest-even

// Orthonormal 8-pt DCT-II butterfly constants (double-derived)
#define CA  0.35355339059327373f
#define CB1 0.46193976625564337f
#define CB3 0.19134171618254492f
#define CD1 0.49039264020161522f
#define CD3 0.41573480615127262f
#define CD5 0.27778511650980114f
#define CD7 0.09754516100806413f

#define FDCT8(x0,x1,x2,x3,x4,x5,x6,x7) do {                                  \
    float e0=(x0)+(x7), e1=(x1)+(x6), e2=(x2)+(x5), e3=(x3)+(x4);            \
    float o0=(x0)-(x7), o1=(x1)-(x6), o2=(x2)-(x5), o3=(x3)-(x4);            \
    float ee0=e0+e3, ee1=e1+e2, eo0=e0-e3, eo1=e1-e2;                        \
    (x0) = CA*(ee0+ee1);                                                     \
    (x4) = CA*(ee0-ee1);                                                     \
    (x2) = CB1*eo0 + CB3*eo1;                                                \
    (x6) = CB3*eo0 - CB1*eo1;                                                \
    (x1) = CD1*o0 + CD3*o1 + CD5*o2 + CD7*o3;                                \
    (x3) = CD3*o0 - CD7*o1 - CD1*o2 - CD5*o3;                                \
    (x5) = CD5*o0 - CD1*o1 + CD7*o2 + CD3*o3;                                \
    (x7) = CD7*o0 - CD5*o1 + CD3*o2 - CD1*o3;                                \
} while(0)

#define IDCT8(x0,x1,x2,x3,x4,x5,x6,x7) do {                                  \
    float ee0 = CA*((x0)+(x4)), ee1 = CA*((x0)-(x4));                        \
    float eo0 = CB1*(x2) + CB3*(x6), eo1 = CB3*(x2) - CB1*(x6);              \
    float o0 = CD1*(x1) + CD3*(x3) + CD5*(x5) + CD7*(x7);                    \
    float o1 = CD3*(x1) - CD7*(x3) - CD1*(x5) - CD5*(x7);                    \
    float o2 = CD5*(x1) - CD1*(x3) + CD7*(x5) + CD3*(x7);                    \
    float o3 = CD7*(x1) - CD5*(x3) + CD3*(x5) - CD1*(x7);                    \
    float e0=ee0+eo0, e3=ee0-eo0, e1=ee1+eo1, e2=ee1-eo1;                    \
    (x0)=e0+o0; (x7)=e0-o0; (x1)=e1+o1; (x6)=e1-o1;                          \
    (x2)=e2+o2; (x5)=e2-o2; (x3)=e3+o3; (x4)=e3-o3;                          \
} while(0)

__constant__ float c_lum[64] = {
    16, 11, 10, 16, 24, 40, 51, 61,
    12, 12, 14, 19, 26, 58, 60, 55,
    14, 13, 16, 24, 40, 57, 69, 56,
    14, 17, 22, 29, 51, 87, 80, 62,
    18, 22, 37, 56, 68, 109, 103, 77,
    24, 35, 55, 64, 81, 104, 113, 92,
    49, 64, 78, 87, 103, 121, 120, 101,
    72, 92, 95, 98, 112, 100, 103, 99
};
__constant__ float c_chrom[64] = {
    17, 18, 24, 47, 99, 99, 99, 99,
    18, 21, 26, 66, 99, 99, 99, 99,
    24, 26, 56, 99, 99, 99, 99, 99,
    47, 66, 99, 99, 99, 99, 99, 99,
    99, 99, 99, 99, 99, 99, 99, 99,
    99, 99, 99, 99, 99, 99, 99, 99,
    99, 99, 99, 99, 99, 99, 99, 99,
    99, 99, 99, 99, 99, 99, 99, 99
};

__global__ void __launch_bounds__(NTHREADS, 2)
jpeg_kernel(const float* __restrict__ img,
            const int* __restrict__ quality,
            float* __restrict__ out)
{
    extern __shared__ float sm[];
    // zipped quant tables: float4 (q0, 1/q0, q1, 1/q1) at float4 index l*5+kp
    __shared__ __align__(16) float qzipL[160];
    __shared__ __align__(16) float qzipC[160];

    const int tid = threadIdx.x;

    // Build tables ONCE per persistent CTA (amortized over ~3.5 tasks)
    if (tid < 256) {
        int t = tid >> 7;                 // 0 lum, 1 chrom
        int rem = tid & 127;
        int l = rem >> 4;
        int kp = (rem >> 2) & 3;
        int comp = rem & 3;               // 0:q0 1:r0 2:q1 3:r1
        int k = 2 * kp + (comp >> 1);
        int q = *quality;
        q = max(1, min(100, q));
        float scale = (q < 50) ? (5000.0f / (float)q) : (200.0f - 2.0f * (float)q);
        float base = t ? c_chrom[k * 8 + l] : c_lum[k * 8 + l];
        float v = (base * scale + 50.0f) / 100.0f;
        v = fminf(fmaxf(v, 1.0f), 255.0f);
        float outv = (comp & 1) ? (1.0f / v) : v;
        (t ? qzipC : qzipL)[(l * 5 + kp) * 4 + comp] = outv;
    }

    const size_t CH = (size_t)IMG_H * IMG_W;

    // quad decomposition (task-invariant)
    const int unit = tid >> 2;          // 0..191 (c*64 + blk)
    const int q = tid & 3;              // row-pair index
    const int c = unit >> 6;
    float* const ub = sm + unit * 72;

    for (int task = blockIdx.x; task < NTASKS; task += NRESIDENT) {
        const int b = task >> 6;
        const int strip = task & 63;
        const int row0 = strip * 8;
        const size_t img_base = (size_t)b * 3 * CH;

        // barrier: previous task's Phase C reads done before overwriting smem
        // (also orders qzip init before first Phase B)
        __syncthreads();

        // ---- Phase A: load + RGB->YCbCr (x255 folded) into block-slot smem --
        #pragma unroll
        for (int g = 0; g < 2; g++) {
            int idx = tid + g * NTHREADS;
            if (idx < 1024) {
                int r = idx >> 7;
                int col = (idx & 127) << 2;
                size_t off = img_base + (size_t)(row0 + r) * IMG_W + col;
                float4 r4 = *(const float4*)(img + off);
                float4 g4 = *(const float4*)(img + off + CH);
                float4 b4 = *(const float4*)(img + off + 2 * CH);
                float4 y4, cb4, cr4;
                {
                    const float* Rp = &r4.x; const float* Gp = &g4.x; const float* Bp = &b4.x;
                    float* Yp = &y4.x; float* Cbp = &cb4.x; float* Crp = &cr4.x;
                    #pragma unroll
                    for (int j = 0; j < 4; j++) {
                        float R = Rp[j], G = Gp[j], B = Bp[j];
                        Yp[j]  = fmaf(76.245f, R, fmaf(149.685f, G, 29.07f * B));
                        Cbp[j] = fmaf(-43.0185f, R, fmaf(-84.4815f, G, fmaf(127.5f, B, 128.0f)));
                        Crp[j] = fmaf(127.5f, R, fmaf(-106.7685f, G, fmaf(-20.7315f, B, 128.0f)));
                    }
                }
                int blk = col >> 3;
                int sb = blk * 72 + (r >> 2) * 36 + (r & 3) * 8 + (col & 7);
                *(float4*)(sm + sb)             = y4;
                *(float4*)(sm + 64 * 72 + sb)   = cb4;
                *(float4*)(sm + 128 * 72 + sb)  = cr4;
            }
        }
        __syncthreads();

        // ---- Phase B: thread quad per 8x8 block ----
        {
            float x[2][8];
            #pragma unroll
            for (int i = 0; i < 2; i++) {
                int a = 2 * q + i;
                float* rp = ub + (a >> 2) * 36 + (a & 3) * 8;
                float4 v0 = *(const float4*)(rp);
                float4 v1 = *(const float4*)(rp + 4);
                x[i][0]=v0.x; x[i][1]=v0.y; x[i][2]=v0.z; x[i][3]=v0.w;
                x[i][4]=v1.x; x[i][5]=v1.y; x[i][6]=v1.z; x[i][7]=v1.w;
            }
            #pragma unroll
            for (int i = 0; i < 2; i++)
                FDCT8(x[i][0],x[i][1],x[i][2],x[i][3],x[i][4],x[i][5],x[i][6],x[i][7]);

            __syncwarp();
            #pragma unroll
            for (int l = 0; l < 8; l++) {
                *(float2*)(ub + (l >> 2) * 36 + (l & 3) * 8 + 2 * q)
                    = make_float2(x[0][l], x[1][l]);
            }
            __syncwarp();

            float y[2][8];
            #pragma unroll
            for (int j = 0; j < 2; j++) {
                int l = 2 * q + j;
                float* rp = ub + (l >> 2) * 36 + (l & 3) * 8;
                float4 v0 = *(const float4*)(rp);
                float4 v1 = *(const float4*)(rp + 4);
                y[j][0]=v0.x; y[j][1]=v0.y; y[j][2]=v0.z; y[j][3]=v0.w;
                y[j][4]=v1.x; y[j][5]=v1.y; y[j][6]=v1.z; y[j][7]=v1.w;
            }
            #pragma unroll
            for (int j = 0; j < 2; j++)
                FDCT8(y[j][0],y[j][1],y[j][2],y[j][3],y[j][4],y[j][5],y[j][6],y[j][7]);

            if (q == 0) y[0][0] -= 1024.0f;   // -128 shift commutes to DC

            {
                const float* qz = ((b * 3 + c) < BATCH) ? qzipL : qzipC;
                #pragma unroll
                for (int j = 0; j < 2; j++) {
                    int l = 2 * q + j;
                    const float4* zl = (const float4*)(qz + l * 20);
                    #pragma unroll
                    for (int kp = 0; kp < 4; kp++) {
                        float4 z = zl[kp];
                        float t0 = fmaf(y[j][2*kp],   z.y, MAGIC);
                        float t1 = fmaf(y[j][2*kp+1], z.w, MAGIC);
                        t0 = __fadd_rn(t0, -MAGIC);
                        t1 = __fadd_rn(t1, -MAGIC);
                        y[j][2*kp]   = t0 * z.x;
                        y[j][2*kp+1] = t1 * z.z;
                    }
                }
            }

            if (q == 0) y[0][0] += 1024.0f;   // +128 shift commutes to DC

            #pragma unroll
            for (int j = 0; j < 2; j++)
                IDCT8(y[j][0],y[j][1],y[j][2],y[j][3],y[j][4],y[j][5],y[j][6],y[j][7]);

            __syncwarp();
            #pragma unroll
            for (int i = 0; i < 8; i++) {
                *(float2*)(ub + (i >> 2) * 36 + (i & 3) * 8 + 2 * q)
                    = make_float2(y[0][i], y[1][i]);
            }
            __syncwarp();

            #pragma unroll
            for (int i = 0; i < 2; i++) {
                int a = 2 * q + i;
                float* rp = ub + (a >> 2) * 36 + (a & 3) * 8;
                float4 v0 = *(const float4*)(rp);
                float4 v1 = *(const float4*)(rp + 4);
                x[i][0]=v0.x; x[i][1]=v0.y; x[i][2]=v0.z; x[i][3]=v0.w;
                x[i][4]=v1.x; x[i][5]=v1.y; x[i][6]=v1.z; x[i][7]=v1.w;
            }
            #pragma unroll
            for (int i = 0; i < 2; i++)
                IDCT8(x[i][0],x[i][1],x[i][2],x[i][3],x[i][4],x[i][5],x[i][6],x[i][7]);

            #pragma unroll
            for (int i = 0; i < 2; i++) {
                int a = 2 * q + i;
                float* rp = ub + (a >> 2) * 36 + (a & 3) * 8;
                *(float4*)(rp)     = make_float4(x[i][0],x[i][1],x[i][2],x[i][3]);
                *(float4*)(rp + 4) = make_float4(x[i][4],x[i][5],x[i][6],x[i][7]);
            }
        }
        __syncthreads();

        // ---- Phase C: YCbCr->RGB, clip, store ----
        #pragma unroll
        for (int g = 0; g < 2; g++) {
            int idx = tid + g * NTHREADS;
            if (idx < 1024) {
                int r = idx >> 7;
                int col = (idx & 127) << 2;
                int blk = col >> 3;
                int sb = blk * 72 + (r >> 2) * 36 + (r & 3) * 8 + (col & 7);
                float4 y4  = *(const float4*)(sm + sb);
                float4 cb4 = *(const float4*)(sm + 64 * 72 + sb);
                float4 cr4 = *(const float4*)(sm + 128 * 72 + sb);
                float4 ro, go, bo;
                {
                    const float* Yp = &y4.x; const float* Cbp = &cb4.x; const float* Crp = &cr4.x;
                    float* Rp = &ro.x; float* Gp = &go.x; float* Bp = &bo.x;
                    #pragma unroll
                    for (int j = 0; j < 4; j++) {
                        float y  = Yp[j];
                        float cb = Cbp[j] - 128.0f;
                        float cr = Crp[j] - 128.0f;
                        float rr = y + 1.402f * cr;
                        float gg = y - 0.34414f * cb - 0.71414f * cr;
                        float bb = y + 1.772f * cb;
                        Rp[j] = fminf(fmaxf(rr * (1.0f / 255.0f), 0.0f), 1.0f);
                        Gp[j] = fminf(fmaxf(gg * (1.0f / 255.0f), 0.0f), 1.0f);
                        Bp[j] = fminf(fmaxf(bb * (1.0f / 255.0f), 0.0f), 1.0f);
                    }
                }
                size_t off = img_base + (size_t)(row0 + r) * IMG_W + col;
                *(float4*)(out + off)          = ro;
                *(float4*)(out + off + CH)     = go;
                *(float4*)(out + off + 2 * CH) = bo;
            }
        }
    }
}

extern "C" void kernel_launch(void* const* d_in, const int* in_sizes, int n_in,
                              void* d_out, int out_size)
{
    const float* img = (const float*)d_in[0];
    const int* quality = (const int*)d_in[1];
    float* out = (float*)d_out;

    cudaFuncSetAttribute(jpeg_kernel,
                         cudaFuncAttributeMaxDynamicSharedMemorySize,
                         SMEM_BYTES);

    dim3 grid(NRESIDENT);   // 296 persistent CTAs (148 SMs x 2)
    jpeg_kernel<<<grid, NTHREADS, SMEM_BYTES>>>(img, quality, out);
}